// round 10
// baseline (speedup 1.0000x reference)
#include <cuda_runtime.h>

// LSTM_87067577025240 — Round 5: eliminate operand-duplication MOVs.
// R4 ncu: alu=34.6% — pack2(w,w) costs 8 MOVs/k. Fix: pair accumulators over
// GATES ({g,i},{f,o}) so FFMA2's 'a' operand is the natural low/high u64 of the
// float4 weight load (zero packing), and keep h PRE-DUPLICATED in smem so 'b'
// operands come straight from LDS.128 ({h_j,h_j,h_j+1,h_j+1}).
//   * per k: 1 LDG.128 + 7 LDS.128 + 28 FFMA2, no MOVs
//   * PF=4 register prefetch ring on weights (validated in R4)
//   * 147 CTAs (NB=14) on 148 SMs; c state in smem; exact-fp32 nonlinearities

#define SEQ   256
#define H     512
#define B_TOT 2048
#define C_OUT 10
#define NB    14                          // batch columns per CTA
#define ROW_U64 16                        // hs2 row stride in u64 (128B rows)
#define NCTA  ((B_TOT + NB - 1) / NB)     // 147
#define NPAIR (NB / 2)                    // 7 LDS.128 per k
#define PF    4                           // weight prefetch depth

typedef unsigned long long u64;

// Gate-fused transposed weights, padded by PF rows for the prefetch ring:
// g_Wt[k*H + t] = {wgh[t][k], wih[t][k], wfh[t][k], woh[t][k]}
// Loaded as ulonglong2: .x = {wg,wi}, .y = {wf,wo} — FFMA2 'a' operands as-is.
__device__ __align__(16) float4 g_Wt[(H + PF) * H];

__device__ __forceinline__ u64 pack2(float lo, float hi) {
    u64 r;
    asm("mov.b64 %0, {%1, %2};" : "=l"(r) : "f"(lo), "f"(hi));
    return r;
}
__device__ __forceinline__ void unpack2(u64 v, float &lo, float &hi) {
    asm("mov.b64 {%0, %1}, %2;" : "=f"(lo), "=f"(hi) : "l"(v));
}
__device__ __forceinline__ u64 fma2(u64 a, u64 b, u64 c) {
    u64 d;
    asm("fma.rn.f32x2 %0, %1, %2, %3;" : "=l"(d) : "l"(a), "l"(b), "l"(c));
    return d;
}

// sigmoid / tanh built on MUFU.EX2 (rel err ~2^-22); avoids tanh.approx (2^-11)
// whose error would compound over 256 recurrent steps. MUFU cost is ~2% — keep exact.
__device__ __forceinline__ float sigmoid_f(float x) {
    return 1.0f / (1.0f + __expf(-x));
}
__device__ __forceinline__ float tanh_f(float x) {
    float ax = fabsf(x);
    float e  = __expf(-2.0f * ax);
    float t  = (1.0f - e) / (1.0f + e);
    return copysignf(t, x);
}

__global__ void prepack_kernel(const float* __restrict__ wgh,
                               const float* __restrict__ wih,
                               const float* __restrict__ wfh,
                               const float* __restrict__ woh) {
    int id = blockIdx.x * blockDim.x + threadIdx.x;   // [0, H*H)
    int k  = id & (H - 1);
    int t  = id >> 9;
    g_Wt[k * H + t] = make_float4(wgh[t * H + k], wih[t * H + k],
                                  wfh[t * H + k], woh[t * H + k]);
}

__global__ __launch_bounds__(H, 1)
void lstm_kernel(const float* __restrict__ x,
                 const float* __restrict__ wgx, const float* __restrict__ wix,
                 const float* __restrict__ wfx, const float* __restrict__ wox,
                 const float* __restrict__ bg,  const float* __restrict__ bi,
                 const float* __restrict__ bf,  const float* __restrict__ bo,
                 const float* __restrict__ wph, const float* __restrict__ bp,
                 const float* __restrict__ h_init, const float* __restrict__ c_init,
                 float* __restrict__ out) {
    extern __shared__ __align__(16) char smem_raw[];
    u64*   hs2 = reinterpret_cast<u64*>(smem_raw);        // [H][ROW_U64]: hs2[k][j]={h,h}
    float* cs  = reinterpret_cast<float*>(hs2 + H * ROW_U64); // [H][NB] c state
    float* xs  = cs + H * NB;                              // [16] current x per column

    const int t    = threadIdx.x;        // h-row owned by this thread
    const int base = blockIdx.x * NB;    // first batch column of this CTA

    const float wgx_r = wgx[t], wix_r = wix[t], wfx_r = wfx[t], wox_r = wox[t];
    const float bg_r  = bg[t],  bi_r  = bi[t],  bf_r  = bf[t],  bo_r  = bo[t];

    const float h0 = h_init[t];
    const float c0 = c_init[t];
    const u64   h0d = pack2(h0, h0);
#pragma unroll
    for (int j = 0; j < ROW_U64; j++) hs2[t * ROW_U64 + j] = h0d;
#pragma unroll
    for (int j = 0; j < NB; j++)      cs[t * NB + j] = c0;
    if (t < 16) xs[t] = 0.0f;
    __syncthreads();

    const ulonglong2* __restrict__ Wt2 = reinterpret_cast<const ulonglong2*>(g_Wt);

    for (int s = 0; s < SEQ; s++) {
        if (t < NB) {
            const int b = base + t;
            xs[t] = (b < B_TOT) ? x[b * SEQ + s] : 0.0f;
        }

        // acc_gi[j] = {gate_g_acc_j, gate_i_acc_j}, acc_fo[j] = {f, o}
        u64 acc_gi[NB], acc_fo[NB];
#pragma unroll
        for (int j = 0; j < NB; j++) { acc_gi[j] = 0ULL; acc_fo[j] = 0ULL; }

        // prime the prefetch ring: PF weight rows in flight at all times
        ulonglong2 wbuf[PF];
#pragma unroll
        for (int i = 0; i < PF; i++) wbuf[i] = Wt2[i * H + t];

#pragma unroll 1
        for (int kg = 0; kg < H; kg += PF) {
#pragma unroll
            for (int i = 0; i < PF; i++) {
                const int k = kg + i;
                const ulonglong2 w = wbuf[i];         // .x={wg,wi}, .y={wf,wo}
                wbuf[i] = Wt2[(k + PF) * H + t];      // over-reads land in pad rows
                const ulonglong2* hrow = reinterpret_cast<const ulonglong2*>(&hs2[k * ROW_U64]);
#pragma unroll
                for (int jp = 0; jp < NPAIR; jp++) {
                    const ulonglong2 b2 = hrow[jp];   // LDS.128: {h_j,h_j},{h_j+1,h_j+1}
                    acc_gi[2*jp]   = fma2(w.x, b2.x, acc_gi[2*jp]);
                    acc_fo[2*jp]   = fma2(w.y, b2.x, acc_fo[2*jp]);
                    acc_gi[2*jp+1] = fma2(w.x, b2.y, acc_gi[2*jp+1]);
                    acc_fo[2*jp+1] = fma2(w.y, b2.y, acc_fo[2*jp+1]);
                }
            }
        }
        __syncthreads();   // everyone done reading hs2 before we overwrite it

        // elementwise: gates -> (c, h) update for this thread's row
#pragma unroll
        for (int j = 0; j < NB; j++) {
            float pg, pi, pf, po;
            unpack2(acc_gi[j], pg, pi);
            unpack2(acc_fo[j], pf, po);
            const float xv = xs[j];
            const float g = tanh_f   (pg + wgx_r * xv + bg_r);
            const float i = sigmoid_f(pi + wix_r * xv + bi_r);
            const float f = sigmoid_f(pf + wfx_r * xv + bf_r);
            const float o = sigmoid_f(po + wox_r * xv + bo_r);
            float c = cs[t * NB + j];
            c = g * i + c * f;
            cs[t * NB + j] = c;
            const float h = tanh_f(c) * o;
            hs2[t * ROW_U64 + j] = pack2(h, h);       // store pre-duplicated
        }
        __syncthreads();   // hs2(t+1) complete before next step's k-loop / xs write
    }

    // final projection: out[b][c] = wph[c][:] . h[:, b] + bp[c]
    if (t < NB * C_OUT) {
        const int j = t / C_OUT;
        const int c = t - j * C_OUT;
        const int b = base + j;
        if (b < B_TOT) {
            const float* hsf = reinterpret_cast<const float*>(hs2);
            float acc = bp[c];
#pragma unroll 8
            for (int k = 0; k < H; k++)
                acc += wph[c * H + k] * hsf[(k * ROW_U64 + j) * 2];  // lo of {h,h}
            out[b * C_OUT + c] = acc;
        }
    }
}

extern "C" void kernel_launch(void* const* d_in, const int* in_sizes, int n_in,
                              void* d_out, int out_size) {
    const float* x      = (const float*)d_in[0];
    const float* wgx    = (const float*)d_in[1];
    const float* wix    = (const float*)d_in[2];
    const float* wfx    = (const float*)d_in[3];
    const float* wox    = (const float*)d_in[4];
    const float* wgh    = (const float*)d_in[5];
    const float* wih    = (const float*)d_in[6];
    const float* wfh    = (const float*)d_in[7];
    const float* woh    = (const float*)d_in[8];
    const float* bg     = (const float*)d_in[9];
    const float* bi     = (const float*)d_in[10];
    const float* bf     = (const float*)d_in[11];
    const float* bo     = (const float*)d_in[12];
    const float* wph    = (const float*)d_in[13];
    const float* bp     = (const float*)d_in[14];
    const float* h_init = (const float*)d_in[15];
    const float* c_init = (const float*)d_in[16];
    float* out = (float*)d_out;

    const int smem_bytes = H * ROW_U64 * 8 + H * NB * 4 + 16 * 4;  // 32KB + 28KB + 64B
    cudaFuncSetAttribute(lstm_kernel, cudaFuncAttributeMaxDynamicSharedMemorySize, smem_bytes);

    prepack_kernel<<<(H * H) / 256, 256>>>(wgh, wih, wfh, woh);
    lstm_kernel<<<NCTA, H, smem_bytes>>>(x, wgx, wix, wfx, wox, bg, bi, bf, bo,
                                         wph, bp, h_init, c_init, out);
}

// round 11
// speedup vs baseline: 1.0000x; 1.0000x over previous
#include <cuda_runtime.h>

// LSTM_87067577025240 — Round 5: eliminate operand-duplication MOVs.
// R4 ncu: alu=34.6% — pack2(w,w) costs 8 MOVs/k. Fix: pair accumulators over
// GATES ({g,i},{f,o}) so FFMA2's 'a' operand is the natural low/high u64 of the
// float4 weight load (zero packing), and keep h PRE-DUPLICATED in smem so 'b'
// operands come straight from LDS.128 ({h_j,h_j,h_j+1,h_j+1}).
//   * per k: 1 LDG.128 + 7 LDS.128 + 28 FFMA2, no MOVs
//   * PF=4 register prefetch ring on weights (validated in R4)
//   * 147 CTAs (NB=14) on 148 SMs; c state in smem; exact-fp32 nonlinearities

#define SEQ   256
#define H     512
#define B_TOT 2048
#define C_OUT 10
#define NB    14                          // batch columns per CTA
#define ROW_U64 16                        // hs2 row stride in u64 (128B rows)
#define NCTA  ((B_TOT + NB - 1) / NB)     // 147
#define NPAIR (NB / 2)                    // 7 LDS.128 per k
#define PF    4                           // weight prefetch depth

typedef unsigned long long u64;

// Gate-fused transposed weights, padded by PF rows for the prefetch ring:
// g_Wt[k*H + t] = {wgh[t][k], wih[t][k], wfh[t][k], woh[t][k]}
// Loaded as ulonglong2: .x = {wg,wi}, .y = {wf,wo} — FFMA2 'a' operands as-is.
__device__ __align__(16) float4 g_Wt[(H + PF) * H];

__device__ __forceinline__ u64 pack2(float lo, float hi) {
    u64 r;
    asm("mov.b64 %0, {%1, %2};" : "=l"(r) : "f"(lo), "f"(hi));
    return r;
}
__device__ __forceinline__ void unpack2(u64 v, float &lo, float &hi) {
    asm("mov.b64 {%0, %1}, %2;" : "=f"(lo), "=f"(hi) : "l"(v));
}
__device__ __forceinline__ u64 fma2(u64 a, u64 b, u64 c) {
    u64 d;
    asm("fma.rn.f32x2 %0, %1, %2, %3;" : "=l"(d) : "l"(a), "l"(b), "l"(c));
    return d;
}

// sigmoid / tanh built on MUFU.EX2 (rel err ~2^-22); avoids tanh.approx (2^-11)
// whose error would compound over 256 recurrent steps. MUFU cost is ~2% — keep exact.
__device__ __forceinline__ float sigmoid_f(float x) {
    return 1.0f / (1.0f + __expf(-x));
}
__device__ __forceinline__ float tanh_f(float x) {
    float ax = fabsf(x);
    float e  = __expf(-2.0f * ax);
    float t  = (1.0f - e) / (1.0f + e);
    return copysignf(t, x);
}

__global__ void prepack_kernel(const float* __restrict__ wgh,
                               const float* __restrict__ wih,
                               const float* __restrict__ wfh,
                               const float* __restrict__ woh) {
    int id = blockIdx.x * blockDim.x + threadIdx.x;   // [0, H*H)
    int k  = id & (H - 1);
    int t  = id >> 9;
    g_Wt[k * H + t] = make_float4(wgh[t * H + k], wih[t * H + k],
                                  wfh[t * H + k], woh[t * H + k]);
}

__global__ __launch_bounds__(H, 1)
void lstm_kernel(const float* __restrict__ x,
                 const float* __restrict__ wgx, const float* __restrict__ wix,
                 const float* __restrict__ wfx, const float* __restrict__ wox,
                 const float* __restrict__ bg,  const float* __restrict__ bi,
                 const float* __restrict__ bf,  const float* __restrict__ bo,
                 const float* __restrict__ wph, const float* __restrict__ bp,
                 const float* __restrict__ h_init, const float* __restrict__ c_init,
                 float* __restrict__ out) {
    extern __shared__ __align__(16) char smem_raw[];
    u64*   hs2 = reinterpret_cast<u64*>(smem_raw);        // [H][ROW_U64]: hs2[k][j]={h,h}
    float* cs  = reinterpret_cast<float*>(hs2 + H * ROW_U64); // [H][NB] c state
    float* xs  = cs + H * NB;                              // [16] current x per column

    const int t    = threadIdx.x;        // h-row owned by this thread
    const int base = blockIdx.x * NB;    // first batch column of this CTA

    const float wgx_r = wgx[t], wix_r = wix[t], wfx_r = wfx[t], wox_r = wox[t];
    const float bg_r  = bg[t],  bi_r  = bi[t],  bf_r  = bf[t],  bo_r  = bo[t];

    const float h0 = h_init[t];
    const float c0 = c_init[t];
    const u64   h0d = pack2(h0, h0);
#pragma unroll
    for (int j = 0; j < ROW_U64; j++) hs2[t * ROW_U64 + j] = h0d;
#pragma unroll
    for (int j = 0; j < NB; j++)      cs[t * NB + j] = c0;
    if (t < 16) xs[t] = 0.0f;
    __syncthreads();

    const ulonglong2* __restrict__ Wt2 = reinterpret_cast<const ulonglong2*>(g_Wt);

    for (int s = 0; s < SEQ; s++) {
        if (t < NB) {
            const int b = base + t;
            xs[t] = (b < B_TOT) ? x[b * SEQ + s] : 0.0f;
        }

        // acc_gi[j] = {gate_g_acc_j, gate_i_acc_j}, acc_fo[j] = {f, o}
        u64 acc_gi[NB], acc_fo[NB];
#pragma unroll
        for (int j = 0; j < NB; j++) { acc_gi[j] = 0ULL; acc_fo[j] = 0ULL; }

        // prime the prefetch ring: PF weight rows in flight at all times
        ulonglong2 wbuf[PF];
#pragma unroll
        for (int i = 0; i < PF; i++) wbuf[i] = Wt2[i * H + t];

#pragma unroll 1
        for (int kg = 0; kg < H; kg += PF) {
#pragma unroll
            for (int i = 0; i < PF; i++) {
                const int k = kg + i;
                const ulonglong2 w = wbuf[i];         // .x={wg,wi}, .y={wf,wo}
                wbuf[i] = Wt2[(k + PF) * H + t];      // over-reads land in pad rows
                const ulonglong2* hrow = reinterpret_cast<const ulonglong2*>(&hs2[k * ROW_U64]);
#pragma unroll
                for (int jp = 0; jp < NPAIR; jp++) {
                    const ulonglong2 b2 = hrow[jp];   // LDS.128: {h_j,h_j},{h_j+1,h_j+1}
                    acc_gi[2*jp]   = fma2(w.x, b2.x, acc_gi[2*jp]);
                    acc_fo[2*jp]   = fma2(w.y, b2.x, acc_fo[2*jp]);
                    acc_gi[2*jp+1] = fma2(w.x, b2.y, acc_gi[2*jp+1]);
                    acc_fo[2*jp+1] = fma2(w.y, b2.y, acc_fo[2*jp+1]);
                }
            }
        }
        __syncthreads();   // everyone done reading hs2 before we overwrite it

        // elementwise: gates -> (c, h) update for this thread's row
#pragma unroll
        for (int j = 0; j < NB; j++) {
            float pg, pi, pf, po;
            unpack2(acc_gi[j], pg, pi);
            unpack2(acc_fo[j], pf, po);
            const float xv = xs[j];
            const float g = tanh_f   (pg + wgx_r * xv + bg_r);
            const float i = sigmoid_f(pi + wix_r * xv + bi_r);
            const float f = sigmoid_f(pf + wfx_r * xv + bf_r);
            const float o = sigmoid_f(po + wox_r * xv + bo_r);
            float c = cs[t * NB + j];
            c = g * i + c * f;
            cs[t * NB + j] = c;
            const float h = tanh_f(c) * o;
            hs2[t * ROW_U64 + j] = pack2(h, h);       // store pre-duplicated
        }
        __syncthreads();   // hs2(t+1) complete before next step's k-loop / xs write
    }

    // final projection: out[b][c] = wph[c][:] . h[:, b] + bp[c]
    if (t < NB * C_OUT) {
        const int j = t / C_OUT;
        const int c = t - j * C_OUT;
        const int b = base + j;
        if (b < B_TOT) {
            const float* hsf = reinterpret_cast<const float*>(hs2);
            float acc = bp[c];
#pragma unroll 8
            for (int k = 0; k < H; k++)
                acc += wph[c * H + k] * hsf[(k * ROW_U64 + j) * 2];  // lo of {h,h}
            out[b * C_OUT + c] = acc;
        }
    }
}

extern "C" void kernel_launch(void* const* d_in, const int* in_sizes, int n_in,
                              void* d_out, int out_size) {
    const float* x      = (const float*)d_in[0];
    const float* wgx    = (const float*)d_in[1];
    const float* wix    = (const float*)d_in[2];
    const float* wfx    = (const float*)d_in[3];
    const float* wox    = (const float*)d_in[4];
    const float* wgh    = (const float*)d_in[5];
    const float* wih    = (const float*)d_in[6];
    const float* wfh    = (const float*)d_in[7];
    const float* woh    = (const float*)d_in[8];
    const float* bg     = (const float*)d_in[9];
    const float* bi     = (const float*)d_in[10];
    const float* bf     = (const float*)d_in[11];
    const float* bo     = (const float*)d_in[12];
    const float* wph    = (const float*)d_in[13];
    const float* bp     = (const float*)d_in[14];
    const float* h_init = (const float*)d_in[15];
    const float* c_init = (const float*)d_in[16];
    float* out = (float*)d_out;

    const int smem_bytes = H * ROW_U64 * 8 + H * NB * 4 + 16 * 4;  // 32KB + 28KB + 64B
    cudaFuncSetAttribute(lstm_kernel, cudaFuncAttributeMaxDynamicSharedMemorySize, smem_bytes);

    prepack_kernel<<<(H * H) / 256, 256>>>(wgh, wih, wfh, woh);
    lstm_kernel<<<NCTA, H, smem_bytes>>>(x, wgx, wix, wfx, wox, bg, bi, bf, bo,
                                         wph, bp, h_init, c_init, out);
}

// round 12
// speedup vs baseline: 1.3540x; 1.3540x over previous
#include <cuda_runtime.h>

// LSTM_87067577025240 — Round 11: break the 512-thread register ceiling.
// R3/R5 post-mortem: every regression had regs=128 (the 512-thr RF cap) and
// phantom alu%/L1% — spills. Redesign: 256 threads/CTA, each owning TWO h-rows.
// Same FFMA2 issue floor (112 FFMA2 per SMSP per k), but ~170 regs/thread of
// headroom (no spills), 2x FMAs per LDS/pack-MOV, 56 independent acc chains.
//   * R4's validated pieces kept: PF=4 LDG.128 prefetch ring, non-duplicated
//     weights, 147 CTAs (NB=14), cs in smem, exact-fp32 MUFU nonlinearities.

#define SEQ   256
#define H     512
#define B_TOT 2048
#define C_OUT 10
#define NB    14                          // batch columns per CTA
#define NBPAD 16                          // hs row stride (floats)
#define NCTA  ((B_TOT + NB - 1) / NB)     // 147
#define NPAIR (NB / 2)                    // 7 f32x2 pairs
#define PF    4                           // weight prefetch depth
#define NTHR  256                         // threads per CTA (2 rows per thread)

typedef unsigned long long u64;

// Gate-fused transposed weights, padded by PF rows for the prefetch ring:
// g_Wt[k*H + r] = {wgh[r][k], wih[r][k], wfh[r][k], woh[r][k]}
__device__ __align__(16) float4 g_Wt[(H + PF) * H];

__device__ __forceinline__ u64 pack2(float lo, float hi) {
    u64 r;
    asm("mov.b64 %0, {%1, %2};" : "=l"(r) : "f"(lo), "f"(hi));
    return r;
}
__device__ __forceinline__ void unpack2(u64 v, float &lo, float &hi) {
    asm("mov.b64 {%0, %1}, %2;" : "=f"(lo), "=f"(hi) : "l"(v));
}
__device__ __forceinline__ u64 fma2(u64 a, u64 b, u64 c) {
    u64 d;
    asm("fma.rn.f32x2 %0, %1, %2, %3;" : "=l"(d) : "l"(a), "l"(b), "l"(c));
    return d;
}

// sigmoid / tanh on MUFU.EX2 (rel err ~2^-22); avoids tanh.approx (2^-11)
// whose error would compound over 256 recurrent steps.
__device__ __forceinline__ float sigmoid_f(float x) {
    return 1.0f / (1.0f + __expf(-x));
}
__device__ __forceinline__ float tanh_f(float x) {
    float ax = fabsf(x);
    float e  = __expf(-2.0f * ax);
    float t  = (1.0f - e) / (1.0f + e);
    return copysignf(t, x);
}

__global__ void prepack_kernel(const float* __restrict__ wgh,
                               const float* __restrict__ wih,
                               const float* __restrict__ wfh,
                               const float* __restrict__ woh) {
    int id = blockIdx.x * blockDim.x + threadIdx.x;   // [0, H*H)
    int k  = id & (H - 1);
    int r  = id >> 9;
    g_Wt[k * H + r] = make_float4(wgh[r * H + k], wih[r * H + k],
                                  wfh[r * H + k], woh[r * H + k]);
}

__global__ __launch_bounds__(NTHR, 1)
void lstm_kernel(const float* __restrict__ x,
                 const float* __restrict__ wgx, const float* __restrict__ wix,
                 const float* __restrict__ wfx, const float* __restrict__ wox,
                 const float* __restrict__ bg,  const float* __restrict__ bi,
                 const float* __restrict__ bf,  const float* __restrict__ bo,
                 const float* __restrict__ wph, const float* __restrict__ bp,
                 const float* __restrict__ h_init, const float* __restrict__ c_init,
                 float* __restrict__ out) {
    extern __shared__ __align__(16) float smem[];
    float* hs = smem;              // [H][NBPAD] h state, broadcast-read in k-loop
    float* cs = smem + H * NBPAD;  // [H][NB]    c state
    float* xs = cs + H * NB;       // [NBPAD]    current x per column

    const int t    = threadIdx.x;        // owns h-rows rA = t, rB = t + 256
    const int rA   = t;
    const int rB   = t + NTHR;
    const int base = blockIdx.x * NB;    // first batch column of this CTA

    // per-row constants for both rows
    const float wgxA = wgx[rA], wixA = wix[rA], wfxA = wfx[rA], woxA = wox[rA];
    const float bgA  = bg[rA],  biA  = bi[rA],  bfA  = bf[rA],  boA  = bo[rA];
    const float wgxB = wgx[rB], wixB = wix[rB], wfxB = wfx[rB], woxB = wox[rB];
    const float bgB  = bg[rB],  biB  = bi[rB],  bfB  = bf[rB],  boB  = bo[rB];

    {
        const float h0A = h_init[rA], c0A = c_init[rA];
        const float h0B = h_init[rB], c0B = c_init[rB];
#pragma unroll
        for (int j = 0; j < NBPAD; j++) { hs[rA * NBPAD + j] = h0A; hs[rB * NBPAD + j] = h0B; }
#pragma unroll
        for (int j = 0; j < NB; j++)    { cs[rA * NB + j] = c0A;    cs[rB * NB + j] = c0B; }
        if (t < NBPAD) xs[t] = 0.0f;
    }
    __syncthreads();

    const float4* __restrict__ Wt = g_Wt;

    for (int s = 0; s < SEQ; s++) {
        if (t < NB) {
            const int b = base + t;
            xs[t] = (b < B_TOT) ? x[b * SEQ + s] : 0.0f;
        }

        u64 agA[NPAIR], aiA[NPAIR], afA[NPAIR], aoA[NPAIR];
        u64 agB[NPAIR], aiB[NPAIR], afB[NPAIR], aoB[NPAIR];
#pragma unroll
        for (int jp = 0; jp < NPAIR; jp++) {
            agA[jp] = 0ULL; aiA[jp] = 0ULL; afA[jp] = 0ULL; aoA[jp] = 0ULL;
            agB[jp] = 0ULL; aiB[jp] = 0ULL; afB[jp] = 0ULL; aoB[jp] = 0ULL;
        }

        // prime the prefetch ring: PF weight rows per owned h-row in flight
        float4 wbufA[PF], wbufB[PF];
#pragma unroll
        for (int i = 0; i < PF; i++) {
            wbufA[i] = Wt[i * H + rA];
            wbufB[i] = Wt[i * H + rB];
        }

#pragma unroll 1
        for (int kg = 0; kg < H; kg += PF) {
#pragma unroll
            for (int i = 0; i < PF; i++) {
                const int k = kg + i;
                const float4 wA = wbufA[i];
                const float4 wB = wbufB[i];
                wbufA[i] = Wt[(k + PF) * H + rA];   // over-reads land in pad rows
                wbufB[i] = Wt[(k + PF) * H + rB];
                const u64 wg2A = pack2(wA.x, wA.x), wi2A = pack2(wA.y, wA.y);
                const u64 wf2A = pack2(wA.z, wA.z), wo2A = pack2(wA.w, wA.w);
                const u64 wg2B = pack2(wB.x, wB.x), wi2B = pack2(wB.y, wB.y);
                const u64 wf2B = pack2(wB.z, wB.z), wo2B = pack2(wB.w, wB.w);
                const float* hrow = &hs[k * NBPAD];
                const ulonglong2 h01 = *reinterpret_cast<const ulonglong2*>(hrow);     // LDS.128 bcast
                const ulonglong2 h23 = *reinterpret_cast<const ulonglong2*>(hrow + 4);
                const ulonglong2 h45 = *reinterpret_cast<const ulonglong2*>(hrow + 8);
                const u64        h6  = *reinterpret_cast<const u64*>(hrow + 12);       // LDS.64
                const u64 hp[NPAIR] = { h01.x, h01.y, h23.x, h23.y, h45.x, h45.y, h6 };
#pragma unroll
                for (int jp = 0; jp < NPAIR; jp++) {
                    const u64 h2 = hp[jp];
                    agA[jp] = fma2(wg2A, h2, agA[jp]);
                    aiA[jp] = fma2(wi2A, h2, aiA[jp]);
                    afA[jp] = fma2(wf2A, h2, afA[jp]);
                    aoA[jp] = fma2(wo2A, h2, aoA[jp]);
                    agB[jp] = fma2(wg2B, h2, agB[jp]);
                    aiB[jp] = fma2(wi2B, h2, aiB[jp]);
                    afB[jp] = fma2(wf2B, h2, afB[jp]);
                    aoB[jp] = fma2(wo2B, h2, aoB[jp]);
                }
            }
        }
        __syncthreads();   // everyone done reading hs before we overwrite it

        // elementwise: gates -> (c, h) update for both owned rows
#pragma unroll
        for (int row = 0; row < 2; row++) {
            const int   r    = row ? rB : rA;
            const float wgxr = row ? wgxB : wgxA, wixr = row ? wixB : wixA;
            const float wfxr = row ? wfxB : wfxA, woxr = row ? woxB : woxA;
            const float bgr  = row ? bgB : bgA,   bir  = row ? biB : biA;
            const float bfr  = row ? bfB : bfA,   bor  = row ? boB : boA;
            u64* ag = row ? agB : agA; u64* ai = row ? aiB : aiA;
            u64* af = row ? afB : afA; u64* ao = row ? aoB : aoA;
#pragma unroll
            for (int jp = 0; jp < NPAIR; jp++) {
                float pg0, pg1, pi0, pi1, pf0, pf1, po0, po1;
                unpack2(ag[jp], pg0, pg1);
                unpack2(ai[jp], pi0, pi1);
                unpack2(af[jp], pf0, pf1);
                unpack2(ao[jp], po0, po1);
#pragma unroll
                for (int hh = 0; hh < 2; hh++) {
                    const int j  = jp * 2 + hh;
                    const float pg = (hh ? pg1 : pg0);
                    const float pi = (hh ? pi1 : pi0);
                    const float pf = (hh ? pf1 : pf0);
                    const float po = (hh ? po1 : po0);
                    const float xv = xs[j];
                    const float g = tanh_f   (pg + wgxr * xv + bgr);
                    const float i = sigmoid_f(pi + wixr * xv + bir);
                    const float f = sigmoid_f(pf + wfxr * xv + bfr);
                    const float o = sigmoid_f(po + woxr * xv + bor);
                    float c = cs[r * NB + j];
                    c = g * i + c * f;
                    cs[r * NB + j] = c;
                    hs[r * NBPAD + j] = tanh_f(c) * o;
                }
            }
        }
        __syncthreads();   // hs(t+1) complete before next step's k-loop / xs write
    }

    // final projection: out[b][c] = wph[c][:] . h[:, b] + bp[c]
    if (t < NB * C_OUT) {
        const int j = t / C_OUT;
        const int c = t - j * C_OUT;
        const int b = base + j;
        if (b < B_TOT) {
            float acc = bp[c];
#pragma unroll 8
            for (int k = 0; k < H; k++) acc += wph[c * H + k] * hs[k * NBPAD + j];
            out[b * C_OUT + c] = acc;
        }
    }
}

extern "C" void kernel_launch(void* const* d_in, const int* in_sizes, int n_in,
                              void* d_out, int out_size) {
    const float* x      = (const float*)d_in[0];
    const float* wgx    = (const float*)d_in[1];
    const float* wix    = (const float*)d_in[2];
    const float* wfx    = (const float*)d_in[3];
    const float* wox    = (const float*)d_in[4];
    const float* wgh    = (const float*)d_in[5];
    const float* wih    = (const float*)d_in[6];
    const float* wfh    = (const float*)d_in[7];
    const float* woh    = (const float*)d_in[8];
    const float* bg     = (const float*)d_in[9];
    const float* bi     = (const float*)d_in[10];
    const float* bf     = (const float*)d_in[11];
    const float* bo     = (const float*)d_in[12];
    const float* wph    = (const float*)d_in[13];
    const float* bp     = (const float*)d_in[14];
    const float* h_init = (const float*)d_in[15];
    const float* c_init = (const float*)d_in[16];
    float* out = (float*)d_out;

    const int smem_bytes = (H * NBPAD + H * NB + NBPAD) * (int)sizeof(float); // ~61.5KB
    cudaFuncSetAttribute(lstm_kernel, cudaFuncAttributeMaxDynamicSharedMemorySize, smem_bytes);

    prepack_kernel<<<(H * H) / 256, 256>>>(wgh, wih, wfh, woh);
    lstm_kernel<<<NCTA, NTHR, smem_bytes>>>(x, wgx, wix, wfx, wox, bg, bi, bf, bo,
                                            wph, bp, h_init, c_init, out);
}

// round 13
// speedup vs baseline: 1.3550x; 1.0007x over previous
#include <cuda_runtime.h>

// LSTM_87067577025240 — Round 11: break the 512-thread register ceiling.
// R3/R5 post-mortem: every regression had regs=128 (the 512-thr RF cap) and
// phantom alu%/L1% — spills. Redesign: 256 threads/CTA, each owning TWO h-rows.
// Same FFMA2 issue floor (112 FFMA2 per SMSP per k), but ~170 regs/thread of
// headroom (no spills), 2x FMAs per LDS/pack-MOV, 56 independent acc chains.
//   * R4's validated pieces kept: PF=4 LDG.128 prefetch ring, non-duplicated
//     weights, 147 CTAs (NB=14), cs in smem, exact-fp32 MUFU nonlinearities.

#define SEQ   256
#define H     512
#define B_TOT 2048
#define C_OUT 10
#define NB    14                          // batch columns per CTA
#define NBPAD 16                          // hs row stride (floats)
#define NCTA  ((B_TOT + NB - 1) / NB)     // 147
#define NPAIR (NB / 2)                    // 7 f32x2 pairs
#define PF    4                           // weight prefetch depth
#define NTHR  256                         // threads per CTA (2 rows per thread)

typedef unsigned long long u64;

// Gate-fused transposed weights, padded by PF rows for the prefetch ring:
// g_Wt[k*H + r] = {wgh[r][k], wih[r][k], wfh[r][k], woh[r][k]}
__device__ __align__(16) float4 g_Wt[(H + PF) * H];

__device__ __forceinline__ u64 pack2(float lo, float hi) {
    u64 r;
    asm("mov.b64 %0, {%1, %2};" : "=l"(r) : "f"(lo), "f"(hi));
    return r;
}
__device__ __forceinline__ void unpack2(u64 v, float &lo, float &hi) {
    asm("mov.b64 {%0, %1}, %2;" : "=f"(lo), "=f"(hi) : "l"(v));
}
__device__ __forceinline__ u64 fma2(u64 a, u64 b, u64 c) {
    u64 d;
    asm("fma.rn.f32x2 %0, %1, %2, %3;" : "=l"(d) : "l"(a), "l"(b), "l"(c));
    return d;
}

// sigmoid / tanh on MUFU.EX2 (rel err ~2^-22); avoids tanh.approx (2^-11)
// whose error would compound over 256 recurrent steps.
__device__ __forceinline__ float sigmoid_f(float x) {
    return 1.0f / (1.0f + __expf(-x));
}
__device__ __forceinline__ float tanh_f(float x) {
    float ax = fabsf(x);
    float e  = __expf(-2.0f * ax);
    float t  = (1.0f - e) / (1.0f + e);
    return copysignf(t, x);
}

__global__ void prepack_kernel(const float* __restrict__ wgh,
                               const float* __restrict__ wih,
                               const float* __restrict__ wfh,
                               const float* __restrict__ woh) {
    int id = blockIdx.x * blockDim.x + threadIdx.x;   // [0, H*H)
    int k  = id & (H - 1);
    int r  = id >> 9;
    g_Wt[k * H + r] = make_float4(wgh[r * H + k], wih[r * H + k],
                                  wfh[r * H + k], woh[r * H + k]);
}

__global__ __launch_bounds__(NTHR, 1)
void lstm_kernel(const float* __restrict__ x,
                 const float* __restrict__ wgx, const float* __restrict__ wix,
                 const float* __restrict__ wfx, const float* __restrict__ wox,
                 const float* __restrict__ bg,  const float* __restrict__ bi,
                 const float* __restrict__ bf,  const float* __restrict__ bo,
                 const float* __restrict__ wph, const float* __restrict__ bp,
                 const float* __restrict__ h_init, const float* __restrict__ c_init,
                 float* __restrict__ out) {
    extern __shared__ __align__(16) float smem[];
    float* hs = smem;              // [H][NBPAD] h state, broadcast-read in k-loop
    float* cs = smem + H * NBPAD;  // [H][NB]    c state
    float* xs = cs + H * NB;       // [NBPAD]    current x per column

    const int t    = threadIdx.x;        // owns h-rows rA = t, rB = t + 256
    const int rA   = t;
    const int rB   = t + NTHR;
    const int base = blockIdx.x * NB;    // first batch column of this CTA

    // per-row constants for both rows
    const float wgxA = wgx[rA], wixA = wix[rA], wfxA = wfx[rA], woxA = wox[rA];
    const float bgA  = bg[rA],  biA  = bi[rA],  bfA  = bf[rA],  boA  = bo[rA];
    const float wgxB = wgx[rB], wixB = wix[rB], wfxB = wfx[rB], woxB = wox[rB];
    const float bgB  = bg[rB],  biB  = bi[rB],  bfB  = bf[rB],  boB  = bo[rB];

    {
        const float h0A = h_init[rA], c0A = c_init[rA];
        const float h0B = h_init[rB], c0B = c_init[rB];
#pragma unroll
        for (int j = 0; j < NBPAD; j++) { hs[rA * NBPAD + j] = h0A; hs[rB * NBPAD + j] = h0B; }
#pragma unroll
        for (int j = 0; j < NB; j++)    { cs[rA * NB + j] = c0A;    cs[rB * NB + j] = c0B; }
        if (t < NBPAD) xs[t] = 0.0f;
    }
    __syncthreads();

    const float4* __restrict__ Wt = g_Wt;

    for (int s = 0; s < SEQ; s++) {
        if (t < NB) {
            const int b = base + t;
            xs[t] = (b < B_TOT) ? x[b * SEQ + s] : 0.0f;
        }

        u64 agA[NPAIR], aiA[NPAIR], afA[NPAIR], aoA[NPAIR];
        u64 agB[NPAIR], aiB[NPAIR], afB[NPAIR], aoB[NPAIR];
#pragma unroll
        for (int jp = 0; jp < NPAIR; jp++) {
            agA[jp] = 0ULL; aiA[jp] = 0ULL; afA[jp] = 0ULL; aoA[jp] = 0ULL;
            agB[jp] = 0ULL; aiB[jp] = 0ULL; afB[jp] = 0ULL; aoB[jp] = 0ULL;
        }

        // prime the prefetch ring: PF weight rows per owned h-row in flight
        float4 wbufA[PF], wbufB[PF];
#pragma unroll
        for (int i = 0; i < PF; i++) {
            wbufA[i] = Wt[i * H + rA];
            wbufB[i] = Wt[i * H + rB];
        }

#pragma unroll 1
        for (int kg = 0; kg < H; kg += PF) {
#pragma unroll
            for (int i = 0; i < PF; i++) {
                const int k = kg + i;
                const float4 wA = wbufA[i];
                const float4 wB = wbufB[i];
                wbufA[i] = Wt[(k + PF) * H + rA];   // over-reads land in pad rows
                wbufB[i] = Wt[(k + PF) * H + rB];
                const u64 wg2A = pack2(wA.x, wA.x), wi2A = pack2(wA.y, wA.y);
                const u64 wf2A = pack2(wA.z, wA.z), wo2A = pack2(wA.w, wA.w);
                const u64 wg2B = pack2(wB.x, wB.x), wi2B = pack2(wB.y, wB.y);
                const u64 wf2B = pack2(wB.z, wB.z), wo2B = pack2(wB.w, wB.w);
                const float* hrow = &hs[k * NBPAD];
                const ulonglong2 h01 = *reinterpret_cast<const ulonglong2*>(hrow);     // LDS.128 bcast
                const ulonglong2 h23 = *reinterpret_cast<const ulonglong2*>(hrow + 4);
                const ulonglong2 h45 = *reinterpret_cast<const ulonglong2*>(hrow + 8);
                const u64        h6  = *reinterpret_cast<const u64*>(hrow + 12);       // LDS.64
                const u64 hp[NPAIR] = { h01.x, h01.y, h23.x, h23.y, h45.x, h45.y, h6 };
#pragma unroll
                for (int jp = 0; jp < NPAIR; jp++) {
                    const u64 h2 = hp[jp];
                    agA[jp] = fma2(wg2A, h2, agA[jp]);
                    aiA[jp] = fma2(wi2A, h2, aiA[jp]);
                    afA[jp] = fma2(wf2A, h2, afA[jp]);
                    aoA[jp] = fma2(wo2A, h2, aoA[jp]);
                    agB[jp] = fma2(wg2B, h2, agB[jp]);
                    aiB[jp] = fma2(wi2B, h2, aiB[jp]);
                    afB[jp] = fma2(wf2B, h2, afB[jp]);
                    aoB[jp] = fma2(wo2B, h2, aoB[jp]);
                }
            }
        }
        __syncthreads();   // everyone done reading hs before we overwrite it

        // elementwise: gates -> (c, h) update for both owned rows
#pragma unroll
        for (int row = 0; row < 2; row++) {
            const int   r    = row ? rB : rA;
            const float wgxr = row ? wgxB : wgxA, wixr = row ? wixB : wixA;
            const float wfxr = row ? wfxB : wfxA, woxr = row ? woxB : woxA;
            const float bgr  = row ? bgB : bgA,   bir  = row ? biB : biA;
            const float bfr  = row ? bfB : bfA,   bor  = row ? boB : boA;
            u64* ag = row ? agB : agA; u64* ai = row ? aiB : aiA;
            u64* af = row ? afB : afA; u64* ao = row ? aoB : aoA;
#pragma unroll
            for (int jp = 0; jp < NPAIR; jp++) {
                float pg0, pg1, pi0, pi1, pf0, pf1, po0, po1;
                unpack2(ag[jp], pg0, pg1);
                unpack2(ai[jp], pi0, pi1);
                unpack2(af[jp], pf0, pf1);
                unpack2(ao[jp], po0, po1);
#pragma unroll
                for (int hh = 0; hh < 2; hh++) {
                    const int j  = jp * 2 + hh;
                    const float pg = (hh ? pg1 : pg0);
                    const float pi = (hh ? pi1 : pi0);
                    const float pf = (hh ? pf1 : pf0);
                    const float po = (hh ? po1 : po0);
                    const float xv = xs[j];
                    const float g = tanh_f   (pg + wgxr * xv + bgr);
                    const float i = sigmoid_f(pi + wixr * xv + bir);
                    const float f = sigmoid_f(pf + wfxr * xv + bfr);
                    const float o = sigmoid_f(po + woxr * xv + bor);
                    float c = cs[r * NB + j];
                    c = g * i + c * f;
                    cs[r * NB + j] = c;
                    hs[r * NBPAD + j] = tanh_f(c) * o;
                }
            }
        }
        __syncthreads();   // hs(t+1) complete before next step's k-loop / xs write
    }

    // final projection: out[b][c] = wph[c][:] . h[:, b] + bp[c]
    if (t < NB * C_OUT) {
        const int j = t / C_OUT;
        const int c = t - j * C_OUT;
        const int b = base + j;
        if (b < B_TOT) {
            float acc = bp[c];
#pragma unroll 8
            for (int k = 0; k < H; k++) acc += wph[c * H + k] * hs[k * NBPAD + j];
            out[b * C_OUT + c] = acc;
        }
    }
}

extern "C" void kernel_launch(void* const* d_in, const int* in_sizes, int n_in,
                              void* d_out, int out_size) {
    const float* x      = (const float*)d_in[0];
    const float* wgx    = (const float*)d_in[1];
    const float* wix    = (const float*)d_in[2];
    const float* wfx    = (const float*)d_in[3];
    const float* wox    = (const float*)d_in[4];
    const float* wgh    = (const float*)d_in[5];
    const float* wih    = (const float*)d_in[6];
    const float* wfh    = (const float*)d_in[7];
    const float* woh    = (const float*)d_in[8];
    const float* bg     = (const float*)d_in[9];
    const float* bi     = (const float*)d_in[10];
    const float* bf     = (const float*)d_in[11];
    const float* bo     = (const float*)d_in[12];
    const float* wph    = (const float*)d_in[13];
    const float* bp     = (const float*)d_in[14];
    const float* h_init = (const float*)d_in[15];
    const float* c_init = (const float*)d_in[16];
    float* out = (float*)d_out;

    const int smem_bytes = (H * NBPAD + H * NB + NBPAD) * (int)sizeof(float); // ~61.5KB
    cudaFuncSetAttribute(lstm_kernel, cudaFuncAttributeMaxDynamicSharedMemorySize, smem_bytes);

    prepack_kernel<<<(H * H) / 256, 256>>>(wgh, wih, wfh, woh);
    lstm_kernel<<<NCTA, NTHR, smem_bytes>>>(x, wgx, wix, wfx, wox, bg, bi, bf, bo,
                                            wph, bp, h_init, c_init, out);
}